// round 3
// baseline (speedup 1.0000x reference)
#include <cuda_runtime.h>
#include <math_constants.h>

#define DD 256
#define NLIG 2048
#define NPRO 16384
#define NB 32

// ---------------- scratch (static device allocation; no cudaMalloc) ---------
__device__ float g_Q  [NLIG * DD];
__device__ float g_K  [NPRO * DD];
__device__ float g_V  [NPRO * DD];
__device__ float g_Q2 [NPRO * DD];
__device__ float g_K2 [NLIG * DD];
__device__ float g_V2 [NLIG * DD];
__device__ float g_ctxL[NLIG * DD];
__device__ float g_ctxP[NPRO * DD];
__device__ float g_tmpL[NLIG * DD];
__device__ float g_tmpP[NPRO * DD];
__device__ int g_ls[NB], g_lc[NB], g_ps[NB], g_pc[NB];

// ---------------- per-batch contiguous ranges (batch ids are sorted) --------
__global__ void ranges_kernel(const int* __restrict__ lb, const int* __restrict__ pb)
{
    int tid = threadIdx.x;
    if (tid < NB) { g_ls[tid] = 0; g_lc[tid] = 0; g_ps[tid] = 0; g_pc[tid] = 0; }
    __syncthreads();
    for (int i = tid; i < NLIG; i += blockDim.x) {
        int b = lb[i];
        if (i == 0 || lb[i - 1] != b) g_ls[b] = i;
        atomicAdd(&g_lc[b], 1);
    }
    for (int i = tid; i < NPRO; i += blockDim.x) {
        int b = pb[i];
        if (i == 0 || pb[i - 1] != b) g_ps[b] = i;
        atomicAdd(&g_pc[b], 1);
    }
}

// ---------------- Y[N,256] = X[N,256] @ W[256,256]^T  (fp32, register tiled) -
// BM=128, BN=64, BK=16; 256 threads; 8x4 outputs per thread.
#define BM 128
#define BN 64
#define BK 16

__global__ __launch_bounds__(256) void gemm_nt(const float* __restrict__ X,
                                               const float* __restrict__ W,
                                               float* __restrict__ Y)
{
    __shared__ __align__(16) float As[BK][BM + 4];  // stride 132 (16B-aligned rows)
    __shared__ __align__(16) float Bs[BK][BN + 4];  // stride 68

    const int m0 = blockIdx.x * BM;
    const int n0 = blockIdx.y * BN;
    const int tid = threadIdx.x;
    const int tx = tid & 15;   // n direction
    const int ty = tid >> 4;   // m direction

    float acc[8][4];
#pragma unroll
    for (int i = 0; i < 8; ++i)
#pragma unroll
        for (int j = 0; j < 4; ++j) acc[i][j] = 0.f;

    const int arow = tid >> 2;        // 0..63
    const int acol = (tid & 3) * 4;   // 0,4,8,12

    for (int kk = 0; kk < DD; kk += BK) {
        float4 a0 = *(const float4*)(X + (size_t)(m0 + arow) * DD + kk + acol);
        float4 a1 = *(const float4*)(X + (size_t)(m0 + arow + 64) * DD + kk + acol);
        float4 b0 = *(const float4*)(W + (size_t)(n0 + arow) * DD + kk + acol);
        __syncthreads();
        As[acol + 0][arow] = a0.x; As[acol + 1][arow] = a0.y;
        As[acol + 2][arow] = a0.z; As[acol + 3][arow] = a0.w;
        As[acol + 0][arow + 64] = a1.x; As[acol + 1][arow + 64] = a1.y;
        As[acol + 2][arow + 64] = a1.z; As[acol + 3][arow + 64] = a1.w;
        Bs[acol + 0][arow] = b0.x; Bs[acol + 1][arow] = b0.y;
        Bs[acol + 2][arow] = b0.z; Bs[acol + 3][arow] = b0.w;
        __syncthreads();
#pragma unroll
        for (int k = 0; k < BK; ++k) {
            float4 av0 = *(const float4*)&As[k][ty * 8];
            float4 av1 = *(const float4*)&As[k][ty * 8 + 4];
            float4 bv  = *(const float4*)&Bs[k][tx * 4];
            float a[8] = {av0.x, av0.y, av0.z, av0.w, av1.x, av1.y, av1.z, av1.w};
            float b[4] = {bv.x, bv.y, bv.z, bv.w};
#pragma unroll
            for (int i = 0; i < 8; ++i)
#pragma unroll
                for (int j = 0; j < 4; ++j)
                    acc[i][j] = fmaf(a[i], b[j], acc[i][j]);
        }
    }

#pragma unroll
    for (int i = 0; i < 8; ++i) {
        float4 o = make_float4(acc[i][0], acc[i][1], acc[i][2], acc[i][3]);
        *(float4*)(Y + (size_t)(m0 + ty * 8 + i) * DD + n0 + tx * 4) = o;
    }
}

// ---------------- flash attention over block-diagonal mask ------------------
// one warp per query row; K/V restricted to the query's batch range.
__global__ __launch_bounds__(128) void attn_kernel(
    const float* __restrict__ Q, const float* __restrict__ K, const float* __restrict__ V,
    const float* __restrict__ qpos, const float* __restrict__ kpos,
    const int* __restrict__ qbatch, const int* __restrict__ kstart,
    const int* __restrict__ kcount, float* __restrict__ ctx, int NQ)
{
    const int row = blockIdx.x * 4 + (threadIdx.x >> 5);
    if (row >= NQ) return;
    const int lane = threadIdx.x & 31;

    const float inv_scale = 0.0625f;  // 1/sqrt(256)
    float4 q0 = *(const float4*)(Q + (size_t)row * DD + lane * 8);
    float4 q1 = *(const float4*)(Q + (size_t)row * DD + lane * 8 + 4);
    q0.x *= inv_scale; q0.y *= inv_scale; q0.z *= inv_scale; q0.w *= inv_scale;
    q1.x *= inv_scale; q1.y *= inv_scale; q1.z *= inv_scale; q1.w *= inv_scale;

    const float qpx = qpos[row * 3 + 0];
    const float qpy = qpos[row * 3 + 1];
    const float qpz = qpos[row * 3 + 2];

    const int b  = qbatch[row];
    const int js = kstart[b];
    const int je = js + kcount[b];

    float m = -1e30f, l = 0.f;
    float4 a0 = make_float4(0.f, 0.f, 0.f, 0.f);
    float4 a1 = make_float4(0.f, 0.f, 0.f, 0.f);

    for (int j = js; j < je; ++j) {
        const float4* Kj = (const float4*)(K + (size_t)j * DD + lane * 8);
        float4 k0 = Kj[0], k1 = Kj[1];
        float dot = q0.x * k0.x + q0.y * k0.y + q0.z * k0.z + q0.w * k0.w
                  + q1.x * k1.x + q1.y * k1.y + q1.z * k1.z + q1.w * k1.w;
#pragma unroll
        for (int off = 16; off; off >>= 1)
            dot += __shfl_xor_sync(0xffffffffu, dot, off);

        float dx = qpx - kpos[3 * j + 0];
        float dy = qpy - kpos[3 * j + 1];
        float dz = qpz - kpos[3 * j + 2];
        float d2 = fmaxf(dx * dx + dy * dy + dz * dz, 1e-12f);
        float s = dot + __expf(-0.1f * sqrtf(d2));

        float mn   = fmaxf(m, s);
        float corr = __expf(m - mn);
        float p    = __expf(s - mn);
        l = l * corr + p;
        m = mn;

        const float4* Vj = (const float4*)(V + (size_t)j * DD + lane * 8);
        float4 v0 = Vj[0], v1 = Vj[1];
        a0.x = a0.x * corr + p * v0.x; a0.y = a0.y * corr + p * v0.y;
        a0.z = a0.z * corr + p * v0.z; a0.w = a0.w * corr + p * v0.w;
        a1.x = a1.x * corr + p * v1.x; a1.y = a1.y * corr + p * v1.y;
        a1.z = a1.z * corr + p * v1.z; a1.w = a1.w * corr + p * v1.w;
    }

    float inv = 1.0f / l;
    a0.x *= inv; a0.y *= inv; a0.z *= inv; a0.w *= inv;
    a1.x *= inv; a1.y *= inv; a1.z *= inv; a1.w *= inv;
    *(float4*)(ctx + (size_t)row * DD + lane * 8)     = a0;
    *(float4*)(ctx + (size_t)row * DD + lane * 8 + 4) = a1;
}

// ---------------- residual + bias + layernorm -------------------------------
__global__ __launch_bounds__(128) void ln_kernel(
    const float* __restrict__ x, const float* __restrict__ yproj,
    const float* __restrict__ bias, const float* __restrict__ g,
    const float* __restrict__ bb, float* __restrict__ out, int N)
{
    const int row = blockIdx.x * 4 + (threadIdx.x >> 5);
    if (row >= N) return;
    const int lane = threadIdx.x & 31;

    float t[8];
#pragma unroll
    for (int i = 0; i < 8; ++i) {
        int c = lane * 8 + i;
        t[i] = x[(size_t)row * DD + c] + yproj[(size_t)row * DD + c] + bias[c];
    }
    float s = 0.f;
#pragma unroll
    for (int i = 0; i < 8; ++i) s += t[i];
#pragma unroll
    for (int off = 16; off; off >>= 1) s += __shfl_xor_sync(0xffffffffu, s, off);
    float mu = s * (1.0f / DD);

    float v = 0.f;
#pragma unroll
    for (int i = 0; i < 8; ++i) { float d = t[i] - mu; v += d * d; }
#pragma unroll
    for (int off = 16; off; off >>= 1) v += __shfl_xor_sync(0xffffffffu, v, off);
    float r = rsqrtf(v * (1.0f / DD) + 1e-5f);

#pragma unroll
    for (int i = 0; i < 8; ++i) {
        int c = lane * 8 + i;
        out[(size_t)row * DD + c] = (t[i] - mu) * r * g[c] + bb[c];
    }
}

// ---------------- launch ----------------------------------------------------
extern "C" void kernel_launch(void* const* d_in, const int* in_sizes, int n_in,
                              void* d_out, int out_size)
{
    const float* lig      = (const float*)d_in[0];
    const float* pro      = (const float*)d_in[1];
    const float* lig_pos  = (const float*)d_in[2];
    const float* pro_pos  = (const float*)d_in[3];
    const int*   lig_batch= (const int*)  d_in[4];
    const int*   pro_batch= (const int*)  d_in[5];
    const float* Wq_lig   = (const float*)d_in[6];
    const float* Wk_pro   = (const float*)d_in[7];
    const float* Wv_pro   = (const float*)d_in[8];
    const float* Wq_pro   = (const float*)d_in[9];
    const float* Wk_lig   = (const float*)d_in[10];
    const float* Wv_lig   = (const float*)d_in[11];
    const float* Wout_lig = (const float*)d_in[12];
    const float* bout_lig = (const float*)d_in[13];
    const float* Wout_pro = (const float*)d_in[14];
    const float* bout_pro = (const float*)d_in[15];
    const float* gl       = (const float*)d_in[16];
    const float* bl       = (const float*)d_in[17];
    const float* gp       = (const float*)d_in[18];
    const float* bp       = (const float*)d_in[19];
    float* out = (float*)d_out;

    float *Q, *K, *V, *Q2, *K2, *V2, *ctxL, *ctxP, *tmpL, *tmpP;
    int *ls, *lc, *ps, *pc;
    cudaGetSymbolAddress((void**)&Q,    g_Q);
    cudaGetSymbolAddress((void**)&K,    g_K);
    cudaGetSymbolAddress((void**)&V,    g_V);
    cudaGetSymbolAddress((void**)&Q2,   g_Q2);
    cudaGetSymbolAddress((void**)&K2,   g_K2);
    cudaGetSymbolAddress((void**)&V2,   g_V2);
    cudaGetSymbolAddress((void**)&ctxL, g_ctxL);
    cudaGetSymbolAddress((void**)&ctxP, g_ctxP);
    cudaGetSymbolAddress((void**)&tmpL, g_tmpL);
    cudaGetSymbolAddress((void**)&tmpP, g_tmpP);
    cudaGetSymbolAddress((void**)&ls,   g_ls);
    cudaGetSymbolAddress((void**)&lc,   g_lc);
    cudaGetSymbolAddress((void**)&ps,   g_ps);
    cudaGetSymbolAddress((void**)&pc,   g_pc);

    ranges_kernel<<<1, 256>>>(lig_batch, pro_batch);

    dim3 gl128(NLIG / BM, DD / BN), gp128(NPRO / BM, DD / BN);
    gemm_nt<<<gl128, 256>>>(lig, Wq_lig, Q);
    gemm_nt<<<gp128, 256>>>(pro, Wk_pro, K);
    gemm_nt<<<gp128, 256>>>(pro, Wv_pro, V);
    gemm_nt<<<gp128, 256>>>(pro, Wq_pro, Q2);
    gemm_nt<<<gl128, 256>>>(lig, Wk_lig, K2);
    gemm_nt<<<gl128, 256>>>(lig, Wv_lig, V2);

    attn_kernel<<<NLIG / 4, 128>>>(Q,  K,  V,  lig_pos, pro_pos, lig_batch, ps, pc, ctxL, NLIG);
    attn_kernel<<<NPRO / 4, 128>>>(Q2, K2, V2, pro_pos, lig_pos, pro_batch, ls, lc, ctxP, NPRO);

    gemm_nt<<<gl128, 256>>>(ctxL, Wout_lig, tmpL);
    gemm_nt<<<gp128, 256>>>(ctxP, Wout_pro, tmpP);

    ln_kernel<<<NLIG / 4, 128>>>(lig, tmpL, bout_lig, gl, bl, out, NLIG);
    ln_kernel<<<NPRO / 4, 128>>>(pro, tmpP, bout_pro, gp, bp, out + (size_t)NLIG * DD, NPRO);
}

// round 4
// speedup vs baseline: 1.9858x; 1.9858x over previous
#include <cuda_runtime.h>

#define DD 256
#define NLIG 2048
#define NPRO 16384
#define NB 32
#define TQA 16
#define TKA 32

// ---------------- scratch (static device allocation; no cudaMalloc) ---------
__device__ float g_Q  [NLIG * DD];
__device__ float g_K  [NPRO * DD];
__device__ float g_V  [NPRO * DD];
__device__ float g_Q2 [NPRO * DD];
__device__ float g_K2 [NLIG * DD];
__device__ float g_V2 [NLIG * DD];
__device__ float g_ctxL[NLIG * DD];
__device__ float g_ctxP[NPRO * DD];
__device__ float g_tmpL[NLIG * DD];
__device__ float g_tmpP[NPRO * DD];
__device__ int g_ls[NB], g_lc[NB], g_ps[NB], g_pc[NB];

// ---------------- per-batch ranges via binary search (batch ids sorted) -----
__global__ void ranges_kernel(const int* __restrict__ lb, const int* __restrict__ pb)
{
    int t = threadIdx.x;
    if (t < NB) {
        int b = t;
        int lo = 0, hi = NLIG;
        while (lo < hi) { int mid = (lo + hi) >> 1; if (lb[mid] < b) lo = mid + 1; else hi = mid; }
        int s = lo; hi = NLIG;
        while (lo < hi) { int mid = (lo + hi) >> 1; if (lb[mid] <= b) lo = mid + 1; else hi = mid; }
        g_ls[b] = s; g_lc[b] = lo - s;
    } else if (t < 2 * NB) {
        int b = t - NB;
        int lo = 0, hi = NPRO;
        while (lo < hi) { int mid = (lo + hi) >> 1; if (pb[mid] < b) lo = mid + 1; else hi = mid; }
        int s = lo; hi = NPRO;
        while (lo < hi) { int mid = (lo + hi) >> 1; if (pb[mid] <= b) lo = mid + 1; else hi = mid; }
        g_ps[b] = s; g_pc[b] = lo - s;
    }
}

// ---------------- multi GEMM: Y[side][z] = X[side] @ W[side][z]^T -----------
// BM=128, BN=64, BK=16; 256 threads; 8x4 outputs per thread.
#define BM 128
#define BN 64
#define BK 16

struct GemmMulti {
    const float* X[2];
    const float* W[2][3];
    float*       Y[2][3];
};

__global__ __launch_bounds__(256) void gemm_nt_multi(GemmMulti g)
{
    __shared__ __align__(16) float As[BK][BM + 4];
    __shared__ __align__(16) float Bs[BK][BN + 4];

    const int side = (blockIdx.x >= 16) ? 1 : 0;
    const int mb   = side ? (blockIdx.x - 16) : blockIdx.x;
    const float* __restrict__ X = g.X[side];
    const float* __restrict__ W = g.W[side][blockIdx.z];
    float* __restrict__       Y = g.Y[side][blockIdx.z];

    const int m0 = mb * BM;
    const int n0 = blockIdx.y * BN;
    const int tid = threadIdx.x;
    const int tx = tid & 15;
    const int ty = tid >> 4;

    float acc[8][4];
#pragma unroll
    for (int i = 0; i < 8; ++i)
#pragma unroll
        for (int j = 0; j < 4; ++j) acc[i][j] = 0.f;

    const int arow = tid >> 2;
    const int acol = (tid & 3) * 4;

    for (int kk = 0; kk < DD; kk += BK) {
        float4 a0 = *(const float4*)(X + (size_t)(m0 + arow) * DD + kk + acol);
        float4 a1 = *(const float4*)(X + (size_t)(m0 + arow + 64) * DD + kk + acol);
        float4 b0 = *(const float4*)(W + (size_t)(n0 + arow) * DD + kk + acol);
        __syncthreads();
        As[acol + 0][arow] = a0.x; As[acol + 1][arow] = a0.y;
        As[acol + 2][arow] = a0.z; As[acol + 3][arow] = a0.w;
        As[acol + 0][arow + 64] = a1.x; As[acol + 1][arow + 64] = a1.y;
        As[acol + 2][arow + 64] = a1.z; As[acol + 3][arow + 64] = a1.w;
        Bs[acol + 0][arow] = b0.x; Bs[acol + 1][arow] = b0.y;
        Bs[acol + 2][arow] = b0.z; Bs[acol + 3][arow] = b0.w;
        __syncthreads();
#pragma unroll
        for (int k = 0; k < BK; ++k) {
            float4 av0 = *(const float4*)&As[k][ty * 8];
            float4 av1 = *(const float4*)&As[k][ty * 8 + 4];
            float4 bv  = *(const float4*)&Bs[k][tx * 4];
            float a[8] = {av0.x, av0.y, av0.z, av0.w, av1.x, av1.y, av1.z, av1.w};
            float b[4] = {bv.x, bv.y, bv.z, bv.w};
#pragma unroll
            for (int i = 0; i < 8; ++i)
#pragma unroll
                for (int j = 0; j < 4; ++j)
                    acc[i][j] = fmaf(a[i], b[j], acc[i][j]);
        }
    }

#pragma unroll
    for (int i = 0; i < 8; ++i) {
        float4 o = make_float4(acc[i][0], acc[i][1], acc[i][2], acc[i][3]);
        *(float4*)(Y + (size_t)(m0 + ty * 8 + i) * DD + n0 + tx * 4) = o;
    }
}

// ---------------- tiled flash attention over block-diagonal mask ------------
// TQ=16 queries per block, keys streamed in TK=32 chunks. 256 threads, 8 warps,
// 2 query rows per warp, lane owns d-columns {4*lane..+3, 128+4*lane..+3}.

struct AttnSide {
    const float *Q, *K, *V, *qpos, *kpos;
    const int *qbatch, *kbatch, *kstart, *kcount;
    float* ctx;
    int nblk;
};

// smem floats: Qs 16*256, Ks 32*256 (swizzled), Vs 32*256, Ps 16*36,
// qp 16*4, kp 32*4, qb 16, kb 32  => 21296 floats = 85184 bytes
#define ATTN_SMEM_FLOATS (TQA*256 + 32*256 + 32*256 + TQA*36 + TQA*4 + 32*4 + TQA + 32)
#define ATTN_SMEM_BYTES  (ATTN_SMEM_FLOATS * 4)

__global__ __launch_bounds__(256, 2) void attn_tiled(AttnSide A0, AttnSide A1)
{
    extern __shared__ float sm[];
    float* Qs = sm;                      // [16][256]
    float* Ks = Qs + TQA * 256;          // [32][256] (col4 xor-swizzled by row&7)
    float* Vs = Ks + 32 * 256;           // [32][256]
    float* Ps = Vs + 32 * 256;           // [16][36]
    float* qp = Ps + TQA * 36;           // [16][4]
    float* kp = qp + TQA * 4;            // [32][4]
    int*   qb = (int*)(kp + 32 * 4);     // [16]
    int*   kb = qb + TQA;                // [32]

    const bool first = (blockIdx.x < (unsigned)A0.nblk);
    AttnSide S = first ? A0 : A1;
    const int blk = first ? blockIdx.x : (blockIdx.x - A0.nblk);

    const int tid  = threadIdx.x;
    const int warp = tid >> 5;
    const int lane = tid & 31;
    const int q0   = blk * TQA;

    // stage Q tile (pre-scaled by 1/sqrt(256)), batch ids, positions
    for (int i = tid; i < TQA * 64; i += 256) {
        int r = i >> 6, c4 = i & 63;
        float4 v = *(const float4*)(S.Q + (size_t)(q0 + r) * DD + c4 * 4);
        v.x *= 0.0625f; v.y *= 0.0625f; v.z *= 0.0625f; v.w *= 0.0625f;
        *(float4*)(Qs + r * 256 + c4 * 4) = v;
    }
    if (tid < TQA) {
        int r = q0 + tid;
        qb[tid] = S.qbatch[r];
        qp[tid * 4 + 0] = S.qpos[r * 3 + 0];
        qp[tid * 4 + 1] = S.qpos[r * 3 + 1];
        qp[tid * 4 + 2] = S.qpos[r * 3 + 2];
    }
    __syncthreads();

    const int b0 = qb[0], b1 = qb[TQA - 1];
    const int js = S.kstart[b0];
    const int je = S.kstart[b1] + S.kcount[b1];

    // per-warp softmax state: two query rows
    float m0 = -1e30f, m1 = -1e30f, l0 = 0.f, l1 = 0.f;
    float4 o0a = make_float4(0,0,0,0), o0b = o0a, o1a = o0a, o1b = o0a;

    const int qr0 = warp * 2, qr1 = warp * 2 + 1;
    const float* Qr0 = Qs + qr0 * 256;
    const float* Qr1 = Qs + qr1 * 256;

    for (int j0 = js; j0 < je; j0 += TKA) {
        __syncthreads();   // previous chunk's consumers done with Ks/Vs

        // stage K (swizzled) and V tiles + key batch/pos
        for (int i = tid; i < 32 * 64; i += 256) {
            int r = i >> 6, c4 = i & 63;
            int gj = j0 + r;
            float4 kv = make_float4(0,0,0,0), vv = kv;
            if (gj < je) {
                kv = *(const float4*)(S.K + (size_t)gj * DD + c4 * 4);
                vv = *(const float4*)(S.V + (size_t)gj * DD + c4 * 4);
            }
            *(float4*)(Ks + r * 256 + ((c4 ^ (r & 7)) << 2)) = kv;
            *(float4*)(Vs + r * 256 + (c4 << 2)) = vv;
        }
        if (tid < 32) {
            int gj = j0 + tid;
            if (gj < je) {
                kb[tid] = S.kbatch[gj];
                kp[tid * 4 + 0] = S.kpos[gj * 3 + 0];
                kp[tid * 4 + 1] = S.kpos[gj * 3 + 1];
                kp[tid * 4 + 2] = S.kpos[gj * 3 + 2];
            } else {
                kb[tid] = -1;
                kp[tid * 4 + 0] = 0.f; kp[tid * 4 + 1] = 0.f; kp[tid * 4 + 2] = 0.f;
            }
        }
        __syncthreads();

        // ---- phase A: lane handles key 'lane'; dot with warp's 2 query rows
        const int   kbj = kb[lane];
        const float kpx = kp[lane * 4 + 0];
        const float kpy = kp[lane * 4 + 1];
        const float kpz = kp[lane * 4 + 2];
        const float* Kr = Ks + lane * 256;
        const int sw = lane & 7;

        float s0 = 0.f, s1 = 0.f;
#pragma unroll 16
        for (int k4 = 0; k4 < 64; ++k4) {
            float4 kv = *(const float4*)(Kr + ((k4 ^ sw) << 2));
            float4 qa = *(const float4*)(Qr0 + k4 * 4);
            float4 qc = *(const float4*)(Qr1 + k4 * 4);
            s0 = fmaf(qa.x, kv.x, s0); s0 = fmaf(qa.y, kv.y, s0);
            s0 = fmaf(qa.z, kv.z, s0); s0 = fmaf(qa.w, kv.w, s0);
            s1 = fmaf(qc.x, kv.x, s1); s1 = fmaf(qc.y, kv.y, s1);
            s1 = fmaf(qc.z, kv.z, s1); s1 = fmaf(qc.w, kv.w, s1);
        }

        // row 0 of this warp
        {
            float qx = qp[qr0 * 4], qy = qp[qr0 * 4 + 1], qz = qp[qr0 * 4 + 2];
            int   qbv = qb[qr0];
            float dx = qx - kpx, dy = qy - kpy, dz = qz - kpz;
            float d2 = fmaxf(fmaf(dx, dx, fmaf(dy, dy, dz * dz)), 1e-12f);
            float s = s0 + __expf(-0.1f * sqrtf(d2));
            s = (qbv == kbj) ? s : -1e9f;
            float mx = s;
#pragma unroll
            for (int off = 16; off; off >>= 1) mx = fmaxf(mx, __shfl_xor_sync(0xffffffffu, mx, off));
            float mn = fmaxf(m0, mx);
            float p = __expf(s - mn);
            float sum = p;
#pragma unroll
            for (int off = 16; off; off >>= 1) sum += __shfl_xor_sync(0xffffffffu, sum, off);
            float corr = __expf(m0 - mn);
            l0 = l0 * corr + sum; m0 = mn;
            Ps[qr0 * 36 + lane] = p;
            o0a.x *= corr; o0a.y *= corr; o0a.z *= corr; o0a.w *= corr;
            o0b.x *= corr; o0b.y *= corr; o0b.z *= corr; o0b.w *= corr;
        }
        // row 1 of this warp
        {
            float qx = qp[qr1 * 4], qy = qp[qr1 * 4 + 1], qz = qp[qr1 * 4 + 2];
            int   qbv = qb[qr1];
            float dx = qx - kpx, dy = qy - kpy, dz = qz - kpz;
            float d2 = fmaxf(fmaf(dx, dx, fmaf(dy, dy, dz * dz)), 1e-12f);
            float s = s1 + __expf(-0.1f * sqrtf(d2));
            s = (qbv == kbj) ? s : -1e9f;
            float mx = s;
#pragma unroll
            for (int off = 16; off; off >>= 1) mx = fmaxf(mx, __shfl_xor_sync(0xffffffffu, mx, off));
            float mn = fmaxf(m1, mx);
            float p = __expf(s - mn);
            float sum = p;
#pragma unroll
            for (int off = 16; off; off >>= 1) sum += __shfl_xor_sync(0xffffffffu, sum, off);
            float corr = __expf(m1 - mn);
            l1 = l1 * corr + sum; m1 = mn;
            Ps[qr1 * 36 + lane] = p;
            o1a.x *= corr; o1a.y *= corr; o1a.z *= corr; o1a.w *= corr;
            o1b.x *= corr; o1b.y *= corr; o1b.z *= corr; o1b.w *= corr;
        }
        __syncwarp();

        // ---- phase B: O += P @ V (rank-32 update)
#pragma unroll
        for (int j4 = 0; j4 < 8; ++j4) {
            float4 p0 = *(const float4*)(Ps + qr0 * 36 + j4 * 4);   // broadcast
            float4 p1 = *(const float4*)(Ps + qr1 * 36 + j4 * 4);
#pragma unroll
            for (int jj = 0; jj < 4; ++jj) {
                const float* Vr = Vs + (j4 * 4 + jj) * 256;
                float4 va = *(const float4*)(Vr + lane * 4);
                float4 vb = *(const float4*)(Vr + 128 + lane * 4);
                float pa = (&p0.x)[jj];
                float pb = (&p1.x)[jj];
                o0a.x = fmaf(pa, va.x, o0a.x); o0a.y = fmaf(pa, va.y, o0a.y);
                o0a.z = fmaf(pa, va.z, o0a.z); o0a.w = fmaf(pa, va.w, o0a.w);
                o0b.x = fmaf(pa, vb.x, o0b.x); o0b.y = fmaf(pa, vb.y, o0b.y);
                o0b.z = fmaf(pa, vb.z, o0b.z); o0b.w = fmaf(pa, vb.w, o0b.w);
                o1a.x = fmaf(pb, va.x, o1a.x); o1a.y = fmaf(pb, va.y, o1a.y);
                o1a.z = fmaf(pb, va.z, o1a.z); o1a.w = fmaf(pb, va.w, o1a.w);
                o1b.x = fmaf(pb, vb.x, o1b.x); o1b.y = fmaf(pb, vb.y, o1b.y);
                o1b.z = fmaf(pb, vb.z, o1b.z); o1b.w = fmaf(pb, vb.w, o1b.w);
            }
        }
    }

    // write context
    float inv0 = 1.0f / l0, inv1 = 1.0f / l1;
    o0a.x *= inv0; o0a.y *= inv0; o0a.z *= inv0; o0a.w *= inv0;
    o0b.x *= inv0; o0b.y *= inv0; o0b.z *= inv0; o0b.w *= inv0;
    o1a.x *= inv1; o1a.y *= inv1; o1a.z *= inv1; o1a.w *= inv1;
    o1b.x *= inv1; o1b.y *= inv1; o1b.z *= inv1; o1b.w *= inv1;
    float* c0 = S.ctx + (size_t)(q0 + qr0) * DD;
    float* c1 = S.ctx + (size_t)(q0 + qr1) * DD;
    *(float4*)(c0 + lane * 4)       = o0a;
    *(float4*)(c0 + 128 + lane * 4) = o0b;
    *(float4*)(c1 + lane * 4)       = o1a;
    *(float4*)(c1 + 128 + lane * 4) = o1b;
}

// ---------------- residual + bias + layernorm (both sides, one launch) ------
__global__ __launch_bounds__(128) void ln2_kernel(
    const float* __restrict__ lig, const float* __restrict__ pro,
    const float* __restrict__ tL, const float* __restrict__ tP,
    const float* __restrict__ boutL, const float* __restrict__ boutP,
    const float* __restrict__ gL, const float* __restrict__ bL,
    const float* __restrict__ gP, const float* __restrict__ bP,
    float* __restrict__ out)
{
    const int row = blockIdx.x * 4 + (threadIdx.x >> 5);
    const int lane = threadIdx.x & 31;

    const float *x, *y, *bias, *g, *bb;
    if (row < NLIG) {
        x = lig + (size_t)row * DD; y = tL + (size_t)row * DD;
        bias = boutL; g = gL; bb = bL;
    } else {
        int r = row - NLIG;
        x = pro + (size_t)r * DD; y = tP + (size_t)r * DD;
        bias = boutP; g = gP; bb = bP;
    }

    float t[8];
#pragma unroll
    for (int i = 0; i < 8; ++i) {
        int c = lane * 8 + i;
        t[i] = x[c] + y[c] + bias[c];
    }
    float s = 0.f;
#pragma unroll
    for (int i = 0; i < 8; ++i) s += t[i];
#pragma unroll
    for (int off = 16; off; off >>= 1) s += __shfl_xor_sync(0xffffffffu, s, off);
    float mu = s * (1.0f / DD);

    float v = 0.f;
#pragma unroll
    for (int i = 0; i < 8; ++i) { float d = t[i] - mu; v += d * d; }
#pragma unroll
    for (int off = 16; off; off >>= 1) v += __shfl_xor_sync(0xffffffffu, v, off);
    float r = rsqrtf(v * (1.0f / DD) + 1e-5f);

#pragma unroll
    for (int i = 0; i < 8; ++i) {
        int c = lane * 8 + i;
        out[(size_t)row * DD + c] = (t[i] - mu) * r * g[c] + bb[c];
    }
}

// ---------------- launch ----------------------------------------------------
extern "C" void kernel_launch(void* const* d_in, const int* in_sizes, int n_in,
                              void* d_out, int out_size)
{
    const float* lig      = (const float*)d_in[0];
    const float* pro      = (const float*)d_in[1];
    const float* lig_pos  = (const float*)d_in[2];
    const float* pro_pos  = (const float*)d_in[3];
    const int*   lig_batch= (const int*)  d_in[4];
    const int*   pro_batch= (const int*)  d_in[5];
    const float* Wq_lig   = (const float*)d_in[6];
    const float* Wk_pro   = (const float*)d_in[7];
    const float* Wv_pro   = (const float*)d_in[8];
    const float* Wq_pro   = (const float*)d_in[9];
    const float* Wk_lig   = (const float*)d_in[10];
    const float* Wv_lig   = (const float*)d_in[11];
    const float* Wout_lig = (const float*)d_in[12];
    const float* bout_lig = (const float*)d_in[13];
    const float* Wout_pro = (const float*)d_in[14];
    const float* bout_pro = (const float*)d_in[15];
    const float* gl       = (const float*)d_in[16];
    const float* bl       = (const float*)d_in[17];
    const float* gp       = (const float*)d_in[18];
    const float* bp       = (const float*)d_in[19];
    float* out = (float*)d_out;

    float *Q, *K, *V, *Q2, *K2, *V2, *ctxL, *ctxP, *tmpL, *tmpP;
    int *ls, *lc, *ps, *pc;
    cudaGetSymbolAddress((void**)&Q,    g_Q);
    cudaGetSymbolAddress((void**)&K,    g_K);
    cudaGetSymbolAddress((void**)&V,    g_V);
    cudaGetSymbolAddress((void**)&Q2,   g_Q2);
    cudaGetSymbolAddress((void**)&K2,   g_K2);
    cudaGetSymbolAddress((void**)&V2,   g_V2);
    cudaGetSymbolAddress((void**)&ctxL, g_ctxL);
    cudaGetSymbolAddress((void**)&ctxP, g_ctxP);
    cudaGetSymbolAddress((void**)&tmpL, g_tmpL);
    cudaGetSymbolAddress((void**)&tmpP, g_tmpP);
    cudaGetSymbolAddress((void**)&ls,   g_ls);
    cudaGetSymbolAddress((void**)&lc,   g_lc);
    cudaGetSymbolAddress((void**)&ps,   g_ps);
    cudaGetSymbolAddress((void**)&pc,   g_pc);

    ranges_kernel<<<1, 64>>>(lig_batch, pro_batch);

    // all 6 QKV projections in one launch
    GemmMulti gq;
    gq.X[0] = lig; gq.X[1] = pro;
    gq.W[0][0] = Wq_lig; gq.W[0][1] = Wk_lig; gq.W[0][2] = Wv_lig;
    gq.W[1][0] = Wk_pro; gq.W[1][1] = Wv_pro; gq.W[1][2] = Wq_pro;
    gq.Y[0][0] = Q;  gq.Y[0][1] = K2; gq.Y[0][2] = V2;
    gq.Y[1][0] = K;  gq.Y[1][1] = V;  gq.Y[1][2] = Q2;
    gemm_nt_multi<<<dim3(16 + 128, DD / BN, 3), 256>>>(gq);

    // both attention directions in one launch (long lig blocks first)
    AttnSide aL, aP;
    aL.Q = Q;  aL.K = K;  aL.V = V;  aL.qpos = lig_pos; aL.kpos = pro_pos;
    aL.qbatch = lig_batch; aL.kbatch = pro_batch; aL.kstart = ps; aL.kcount = pc;
    aL.ctx = ctxL; aL.nblk = NLIG / TQA;
    aP.Q = Q2; aP.K = K2; aP.V = V2; aP.qpos = pro_pos; aP.kpos = lig_pos;
    aP.qbatch = pro_batch; aP.kbatch = lig_batch; aP.kstart = ls; aP.kcount = lc;
    aP.ctx = ctxP; aP.nblk = NPRO / TQA;

    cudaFuncSetAttribute(attn_tiled, cudaFuncAttributeMaxDynamicSharedMemorySize, ATTN_SMEM_BYTES);
    attn_tiled<<<NLIG / TQA + NPRO / TQA, 256, ATTN_SMEM_BYTES>>>(aL, aP);

    // both output projections in one launch
    GemmMulti go;
    go.X[0] = ctxL; go.X[1] = ctxP;
    go.W[0][0] = Wout_lig; go.W[0][1] = Wout_lig; go.W[0][2] = Wout_lig;
    go.W[1][0] = Wout_pro; go.W[1][1] = Wout_pro; go.W[1][2] = Wout_pro;
    go.Y[0][0] = tmpL; go.Y[0][1] = tmpL; go.Y[0][2] = tmpL;
    go.Y[1][0] = tmpP; go.Y[1][1] = tmpP; go.Y[1][2] = tmpP;
    gemm_nt_multi<<<dim3(16 + 128, DD / BN, 1), 256>>>(go);

    // both layernorms in one launch
    ln2_kernel<<<(NLIG + NPRO) / 4, 128>>>(lig, pro, tmpL, tmpP,
                                           bout_lig, bout_pro, gl, bl, gp, bp, out);
}

// round 6
// speedup vs baseline: 2.8585x; 1.4395x over previous
#include <cuda_runtime.h>
#include <cuda_bf16.h>
#include <cstdint>

#define DD 256
#define NLIG 2048
#define NPRO 16384
#define NB 32
#define TQA 16
#define TKA 32

__device__ __forceinline__ uint32_t smem_to_u32(const void* p) {
    uint32_t a;
    asm("{ .reg .u64 t; cvta.to.shared.u64 t, %1; cvt.u32.u64 %0, t; }" : "=r"(a) : "l"(p));
    return a;
}

// warp-level bf16 tensor-core MMA (compute_80+; works on plain compute_103)
#define MMA_BF16(c, a, b0v, b1v) \
    asm volatile("mma.sync.aligned.m16n8k16.row.col.f32.bf16.bf16.f32 " \
        "{%0,%1,%2,%3}, {%4,%5,%6,%7}, {%8,%9}, {%0,%1,%2,%3};" \
        : "+f"((c)[0]), "+f"((c)[1]), "+f"((c)[2]), "+f"((c)[3]) \
        : "r"((a)[0]), "r"((a)[1]), "r"((a)[2]), "r"((a)[3]), "r"(b0v), "r"(b1v))

#define LDSM_X4(r, addr) \
    asm volatile("ldmatrix.sync.aligned.m8n8.x4.shared.b16 {%0,%1,%2,%3}, [%4];" \
        : "=r"((r)[0]), "=r"((r)[1]), "=r"((r)[2]), "=r"((r)[3]) : "r"(addr))

// ---------------- scratch (static device allocation; no cudaMalloc) ---------
__device__ float g_Q  [NLIG * DD];
__device__ float g_K  [NPRO * DD];
__device__ float g_V  [NPRO * DD];
__device__ float g_Q2 [NPRO * DD];
__device__ float g_K2 [NLIG * DD];
__device__ float g_V2 [NLIG * DD];
__device__ float g_ctxL[NLIG * DD];
__device__ float g_ctxP[NPRO * DD];
__device__ float g_tmpL[NLIG * DD];
__device__ float g_tmpP[NPRO * DD];
__device__ int g_ls[NB], g_lc[NB], g_ps[NB], g_pc[NB];

// ---------------- per-batch ranges via binary search (batch ids sorted) -----
__global__ void ranges_kernel(const int* __restrict__ lb, const int* __restrict__ pb)
{
    int t = threadIdx.x;
    if (t < NB) {
        int b = t;
        int lo = 0, hi = NLIG;
        while (lo < hi) { int mid = (lo + hi) >> 1; if (lb[mid] < b) lo = mid + 1; else hi = mid; }
        int s = lo; hi = NLIG;
        while (lo < hi) { int mid = (lo + hi) >> 1; if (lb[mid] <= b) lo = mid + 1; else hi = mid; }
        g_ls[b] = s; g_lc[b] = lo - s;
    } else if (t < 2 * NB) {
        int b = t - NB;
        int lo = 0, hi = NPRO;
        while (lo < hi) { int mid = (lo + hi) >> 1; if (pb[mid] < b) lo = mid + 1; else hi = mid; }
        int s = lo; hi = NPRO;
        while (lo < hi) { int mid = (lo + hi) >> 1; if (pb[mid] <= b) lo = mid + 1; else hi = mid; }
        g_ps[b] = s; g_pc[b] = lo - s;
    }
}

// ============ split-bf16 mma.sync GEMM: Y = X @ W^T, fp32 I/O ===============
// CTA: 128x128 output, 8 warps (4 along M x 2 along N), warp tile 32x64.
// K in 4 chunks of 64; fp32 -> bf16 hi/lo split fused into swizzled staging.
// 3 MMA passes per fragment pair: Ah*Bh + Ah*Bl + Al*Bh (fp32 accum).

struct MmaOps {
    const float* X[6];
    const float* W[6];
    float*       Y[6];
    int lig_ops;    // first lig_ops ops have 16 row-tiles, remainder 128
};

// smem: A_hi[128][64]bf16 @0, A_lo @16384, B_hi @32768, B_lo @49152
#define GEMM_SMEM 65536

__device__ __forceinline__ void split2(float a, float b, uint32_t& hi, uint32_t& lo)
{
    __nv_bfloat16 ha = __float2bfloat16(a), hb = __float2bfloat16(b);
    __nv_bfloat162 hp = __halves2bfloat162(ha, hb);
    hi = *reinterpret_cast<uint32_t*>(&hp);
    float la = a - __bfloat162float(ha);
    float lb = b - __bfloat162float(hb);
    __nv_bfloat162 lp = __floats2bfloat162_rn(la, lb);
    lo = *reinterpret_cast<uint32_t*>(&lp);
}

__global__ __launch_bounds__(256) void gemm_mma(MmaOps P)
{
    extern __shared__ char smc[];
    const uint32_t sb = smem_to_u32(smc);

    const int bx = blockIdx.x;
    const int ligregion = P.lig_ops * 16;
    int op, mt;
    if (bx < ligregion) { op = bx >> 4; mt = bx & 15; }
    else { int r = bx - ligregion; op = P.lig_ops + (r >> 7); mt = r & 127; }
    const float* __restrict__ X = P.X[op];
    const float* __restrict__ W = P.W[op];
    float* __restrict__       Y = P.Y[op];
    const int m0 = mt * 128;
    const int n0 = blockIdx.y * 128;

    const int tid = threadIdx.x, lane = tid & 31, wid = tid >> 5;
    const int warpM = wid & 3, warpN = wid >> 2;
    const int sub = lane >> 3, r8 = lane & 7;

    float acc[2][8][4];
#pragma unroll
    for (int i = 0; i < 2; ++i)
#pragma unroll
        for (int j = 0; j < 8; ++j)
#pragma unroll
            for (int k = 0; k < 4; ++k) acc[i][j][k] = 0.f;

    for (int kc = 0; kc < 4; ++kc) {
        // ---- stage chunk: fp32 -> bf16 hi/lo, 16B-xor swizzled ----
#pragma unroll
        for (int it = 0; it < 8; ++it) {
            int idx = tid + it * 256;           // 0..2047
            int r = idx >> 4, c4 = idx & 15;    // col = c4*4
            int byte = ((r * 128 + (c4 >> 1) * 16) ^ ((r & 7) << 4)) + (c4 & 1) * 8;
            float4 f = *(const float4*)(X + (size_t)(m0 + r) * DD + kc * 64 + c4 * 4);
            uint32_t h0, l0, h1, l1;
            split2(f.x, f.y, h0, l0); split2(f.z, f.w, h1, l1);
            *(uint2*)(smc + byte)         = make_uint2(h0, h1);
            *(uint2*)(smc + 16384 + byte) = make_uint2(l0, l1);
            f = *(const float4*)(W + (size_t)(n0 + r) * DD + kc * 64 + c4 * 4);
            split2(f.x, f.y, h0, l0); split2(f.z, f.w, h1, l1);
            *(uint2*)(smc + 32768 + byte) = make_uint2(h0, h1);
            *(uint2*)(smc + 49152 + byte) = make_uint2(l0, l1);
        }
        __syncthreads();

#pragma unroll
        for (int k16 = 0; k16 < 4; ++k16) {
            uint32_t a_hi[2][4], a_lo[2][4];
#pragma unroll
            for (int mt2 = 0; mt2 < 2; ++mt2) {
                int row = warpM * 32 + mt2 * 16 + (sub & 1) * 8 + r8;
                int k8  = k16 * 2 + (sub >> 1);
                uint32_t ad = sb + ((row * 128 + k8 * 16) ^ ((row & 7) << 4));
                LDSM_X4(a_hi[mt2], ad);
                LDSM_X4(a_lo[mt2], ad + 16384);
            }
#pragma unroll
            for (int np = 0; np < 4; ++np) {
                int nrow = warpN * 64 + np * 16 + (sub >> 1) * 8 + r8;
                int k8   = k16 * 2 + (sub & 1);
                uint32_t bd = sb + 32768 + ((nrow * 128 + k8 * 16) ^ ((nrow & 7) << 4));
                uint32_t b_hi[4], b_lo[4];
                LDSM_X4(b_hi, bd);
                LDSM_X4(b_lo, bd + 16384);
#pragma unroll
                for (int mt2 = 0; mt2 < 2; ++mt2) {
                    MMA_BF16(acc[mt2][np * 2],     a_hi[mt2], b_hi[0], b_hi[1]);
                    MMA_BF16(acc[mt2][np * 2 + 1], a_hi[mt2], b_hi[2], b_hi[3]);
                    MMA_BF16(acc[mt2][np * 2],     a_hi[mt2], b_lo[0], b_lo[1]);
                    MMA_BF16(acc[mt2][np * 2 + 1], a_hi[mt2], b_lo[2], b_lo[3]);
                    MMA_BF16(acc[mt2][np * 2],     a_lo[mt2], b_hi[0], b_hi[1]);
                    MMA_BF16(acc[mt2][np * 2 + 1], a_lo[mt2], b_hi[2], b_hi[3]);
                }
            }
        }
        __syncthreads();
    }

    // ---- epilogue: fragment -> GMEM (float2 per row-piece) ----
    const int t4 = lane >> 2, q = lane & 3;
#pragma unroll
    for (int mt2 = 0; mt2 < 2; ++mt2) {
#pragma unroll
        for (int nt = 0; nt < 8; ++nt) {
            float* yr = Y + (size_t)(m0 + warpM * 32 + mt2 * 16 + t4) * DD
                          + n0 + warpN * 64 + nt * 8 + q * 2;
            *(float2*)yr            = make_float2(acc[mt2][nt][0], acc[mt2][nt][1]);
            *(float2*)(yr + 8 * DD) = make_float2(acc[mt2][nt][2], acc[mt2][nt][3]);
        }
    }
}

// ======== tiled flash attention, block-diagonal mask, no-max softmax ========
// scores are bounded (|s| <~ 7) so exp(s) never overflows: skip online max.

struct AttnSide {
    const float *Q, *K, *V, *qpos, *kpos;
    const int *qbatch, *kbatch, *kstart, *kcount;
    float* ctx;
    int nblk;
};

#define ATTN_SMEM_FLOATS (TQA*256 + 32*256 + 32*256 + TQA*36 + TQA*4 + 32*4 + TQA + 32)
#define ATTN_SMEM_BYTES  (ATTN_SMEM_FLOATS * 4)

__global__ __launch_bounds__(256, 2) void attn_tiled(AttnSide A0, AttnSide A1)
{
    extern __shared__ float sm[];
    float* Qs = sm;                      // [16][256]
    float* Ks = Qs + TQA * 256;          // [32][256] (col4 xor-swizzled by row&7)
    float* Vs = Ks + 32 * 256;           // [32][256]
    float* Ps = Vs + 32 * 256;           // [16][36]
    float* qp = Ps + TQA * 36;           // [16][4]
    float* kp = qp + TQA * 4;            // [32][4]
    int*   qb = (int*)(kp + 32 * 4);     // [16]
    int*   kb = qb + TQA;                // [32]

    const bool first = (blockIdx.x < (unsigned)A0.nblk);
    AttnSide S = first ? A0 : A1;
    const int blk = first ? blockIdx.x : (blockIdx.x - A0.nblk);

    const int tid  = threadIdx.x;
    const int warp = tid >> 5;
    const int lane = tid & 31;
    const int q0   = blk * TQA;

    for (int i = tid; i < TQA * 64; i += 256) {
        int r = i >> 6, c4 = i & 63;
        float4 v = *(const float4*)(S.Q + (size_t)(q0 + r) * DD + c4 * 4);
        v.x *= 0.0625f; v.y *= 0.0625f; v.z *= 0.0625f; v.w *= 0.0625f;
        *(float4*)(Qs + r * 256 + c4 * 4) = v;
    }
    if (tid < TQA) {
        int r = q0 + tid;
        qb[tid] = S.qbatch[r];
        qp[tid * 4 + 0] = S.qpos[r * 3 + 0];
        qp[tid * 4 + 1] = S.qpos[r * 3 + 1];
        qp[tid * 4 + 2] = S.qpos[r * 3 + 2];
    }
    __syncthreads();

    const int b0 = qb[0], b1 = qb[TQA - 1];
    const int js = S.kstart[b0];
    const int je = S.kstart[b1] + S.kcount[b1];

    float l0 = 0.f, l1 = 0.f;   // per-lane partial sums (lane owns its keys)
    float4 o0a = make_float4(0,0,0,0), o0b = o0a, o1a = o0a, o1b = o0a;

    const int qr0 = warp * 2, qr1 = warp * 2 + 1;
    const float* Qr0 = Qs + qr0 * 256;
    const float* Qr1 = Qs + qr1 * 256;
    const float q0x = qp[qr0 * 4], q0y = qp[qr0 * 4 + 1], q0z = qp[qr0 * 4 + 2];
    const float q1x = qp[qr1 * 4], q1y = qp[qr1 * 4 + 1], q1z = qp[qr1 * 4 + 2];
    const int qb0 = qb[qr0], qb1 = qb[qr1];

    for (int j0 = js; j0 < je; j0 += TKA) {
        __syncthreads();

        for (int i = tid; i < 32 * 64; i += 256) {
            int r = i >> 6, c4 = i & 63;
            int gj = j0 + r;
            float4 kv = make_float4(0,0,0,0), vv = kv;
            if (gj < je) {
                kv = *(const float4*)(S.K + (size_t)gj * DD + c4 * 4);
                vv = *(const float4*)(S.V + (size_t)gj * DD + c4 * 4);
            }
            *(float4*)(Ks + r * 256 + ((c4 ^ (r & 7)) << 2)) = kv;
            *(float4*)(Vs + r * 256 + (c4 << 2)) = vv;
        }
        if (tid < 32) {
            int gj = j0 + tid;
            if (gj < je) {
                kb[tid] = S.kbatch[gj];
                kp[tid * 4 + 0] = S.kpos[gj * 3 + 0];
                kp[tid * 4 + 1] = S.kpos[gj * 3 + 1];
                kp[tid * 4 + 2] = S.kpos[gj * 3 + 2];
            } else {
                kb[tid] = -1;
                kp[tid * 4 + 0] = 0.f; kp[tid * 4 + 1] = 0.f; kp[tid * 4 + 2] = 0.f;
            }
        }
        __syncthreads();

        // phase A: lane handles key 'lane' for this warp's 2 query rows
        const int   kbj = kb[lane];
        const float kpx = kp[lane * 4 + 0];
        const float kpy = kp[lane * 4 + 1];
        const float kpz = kp[lane * 4 + 2];
        const float* Kr = Ks + lane * 256;
        const int sw = lane & 7;

        float s0 = 0.f, s1 = 0.f;
#pragma unroll 16
        for (int k4 = 0; k4 < 64; ++k4) {
            float4 kv = *(const float4*)(Kr + ((k4 ^ sw) << 2));
            float4 qa = *(const float4*)(Qr0 + k4 * 4);
            float4 qc = *(const float4*)(Qr1 + k4 * 4);
            s0 = fmaf(qa.x, kv.x, s0); s0 = fmaf(qa.y, kv.y, s0);
            s0 = fmaf(qa.z, kv.z, s0); s0 = fmaf(qa.w, kv.w, s0);
            s1 = fmaf(qc.x, kv.x, s1); s1 = fmaf(qc.y, kv.y, s1);
            s1 = fmaf(qc.z, kv.z, s1); s1 = fmaf(qc.w, kv.w, s1);
        }

        {
            float dx = q0x - kpx, dy = q0y - kpy, dz = q0z - kpz;
            float d2 = fmaxf(fmaf(dx, dx, fmaf(dy, dy, dz * dz)), 1e-12f);
            float p = (qb0 == kbj) ? __expf(s0 + __expf(-0.1f * sqrtf(d2))) : 0.f;
            l0 += p;
            Ps[qr0 * 36 + lane] = p;
        }
        {
            float dx = q1x - kpx, dy = q1y - kpy, dz = q1z - kpz;
            float d2 = fmaxf(fmaf(dx, dx, fmaf(dy, dy, dz * dz)), 1e-12f);
            float p = (qb1 == kbj) ? __expf(s1 + __expf(-0.1f * sqrtf(d2))) : 0.f;
            l1 += p;
            Ps[qr1 * 36 + lane] = p;
        }
        __syncwarp();

        // phase B: O += P @ V (rank-32 update)
#pragma unroll
        for (int j4 = 0; j4 < 8; ++j4) {
            float4 p0 = *(const float4*)(Ps + qr0 * 36 + j4 * 4);
            float4 p1 = *(const float4*)(Ps + qr1 * 36 + j4 * 4);
#pragma unroll
            for (int jj = 0; jj < 4; ++jj) {
                const float* Vr = Vs + (j4 * 4 + jj) * 256;
                float4 va = *(const float4*)(Vr + lane * 4);
                float4 vb = *(const float4*)(Vr + 128 + lane * 4);
                float pa = (&p0.x)[jj];
                float pb = (&p1.x)[jj];
                o0a.x = fmaf(pa, va.x, o0a.x); o0a.y = fmaf(pa, va.y, o0a.y);
                o0a.z = fmaf(pa, va.z, o0a.z); o0a.w = fmaf(pa, va.w, o0a.w);
                o0b.x = fmaf(pa, vb.x, o0b.x); o0b.y = fmaf(pa, vb.y, o0b.y);
                o0b.z = fmaf(pa, vb.z, o0b.z); o0b.w = fmaf(pa, vb.w, o0b.w);
                o1a.x = fmaf(pb, va.x, o1a.x); o1a.y = fmaf(pb, va.y, o1a.y);
                o1a.z = fmaf(pb, va.z, o1a.z); o1a.w = fmaf(pb, va.w, o1a.w);
                o1b.x = fmaf(pb, vb.x, o1b.x); o1b.y = fmaf(pb, vb.y, o1b.y);
                o1b.z = fmaf(pb, vb.z, o1b.z); o1b.w = fmaf(pb, vb.w, o1b.w);
            }
        }
    }

    // reduce per-lane sums, normalize, write
#pragma unroll
    for (int off = 16; off; off >>= 1) l0 += __shfl_xor_sync(0xffffffffu, l0, off);
#pragma unroll
    for (int off = 16; off; off >>= 1) l1 += __shfl_xor_sync(0xffffffffu, l1, off);
    float inv0 = 1.0f / l0, inv1 = 1.0f / l1;
    o0a.x *= inv0; o0a.y *= inv0; o0a.z *= inv0; o0a.w *= inv0;
    o0b.x *= inv0; o0b.y *= inv0; o0b.z *= inv0; o0b.w *= inv0;
    o1a.x *= inv1; o1a.y *= inv1; o1a.z *= inv1; o1a.w *= inv1;
    o1b.x *= inv1; o1b.y *= inv1; o1b.z *= inv1; o1b.w *= inv1;
    float* c0 = S.ctx + (size_t)(q0 + qr0) * DD;
    float* c1 = S.ctx + (size_t)(q0 + qr1) * DD;
    *(float4*)(c0 + lane * 4)       = o0a;
    *(float4*)(c0 + 128 + lane * 4) = o0b;
    *(float4*)(c1 + lane * 4)       = o1a;
    *(float4*)(c1 + 128 + lane * 4) = o1b;
}

// ---------------- residual + bias + layernorm (both sides, one launch) ------
__global__ __launch_bounds__(128) void ln2_kernel(
    const float* __restrict__ lig, const float* __restrict__ pro,
    const float* __restrict__ tL, const float* __restrict__ tP,
    const float* __restrict__ boutL, const float* __restrict__ boutP,
    const float* __restrict__ gL, const float* __restrict__ bL,
    const float* __restrict__ gP, const float* __restrict__ bP,
    float* __restrict__ out)
{
    const int row = blockIdx.x * 4 + (threadIdx.x >> 5);
    const int lane = threadIdx.x & 31;

    const float *x, *y, *bias, *g, *bb;
    if (row < NLIG) {
        x = lig + (size_t)row * DD; y = tL + (size_t)row * DD;
        bias = boutL; g = gL; bb = bL;
    } else {
        int r = row - NLIG;
        x = pro + (size_t)r * DD; y = tP + (size_t)r * DD;
        bias = boutP; g = gP; bb = bP;
    }

    float t[8];
#pragma unroll
    for (int i = 0; i < 8; ++i) {
        int c = lane * 8 + i;
        t[i] = x[c] + y[c] + bias[c];
    }
    float s = 0.f;
#pragma unroll
    for (int i = 0; i < 8; ++i) s += t[i];
#pragma unroll
    for (int off = 16; off; off >>= 1) s += __shfl_xor_sync(0xffffffffu, s, off);
    float mu = s * (1.0f / DD);

    float v = 0.f;
#pragma unroll
    for (int i = 0; i < 8; ++i) { float d = t[i] - mu; v += d * d; }
#pragma unroll
    for (int off = 16; off; off >>= 1) v += __shfl_xor_sync(0xffffffffu, v, off);
    float r = rsqrtf(v * (1.0f / DD) + 1e-5f);

#pragma unroll
    for (int i = 0; i < 8; ++i) {
        int c = lane * 8 + i;
        out[(size_t)row * DD + c] = (t[i] - mu) * r * g[c] + bb[c];
    }
}

// ---------------- launch ----------------------------------------------------
extern "C" void kernel_launch(void* const* d_in, const int* in_sizes, int n_in,
                              void* d_out, int out_size)
{
    const float* lig      = (const float*)d_in[0];
    const float* pro      = (const float*)d_in[1];
    const float* lig_pos  = (const float*)d_in[2];
    const float* pro_pos  = (const float*)d_in[3];
    const int*   lig_batch= (const int*)  d_in[4];
    const int*   pro_batch= (const int*)  d_in[5];
    const float* Wq_lig   = (const float*)d_in[6];
    const float* Wk_pro   = (const float*)d_in[7];
    const float* Wv_pro   = (const float*)d_in[8];
    const float* Wq_pro   = (const float*)d_in[9];
    const float* Wk_lig   = (const float*)d_in[10];
    const float* Wv_lig   = (const float*)d_in[11];
    const float* Wout_lig = (const float*)d_in[12];
    const float* bout_lig = (const float*)d_in[13];
    const float* Wout_pro = (const float*)d_in[14];
    const float* bout_pro = (const float*)d_in[15];
    const float* gl       = (const float*)d_in[16];
    const float* bl       = (const float*)d_in[17];
    const float* gp       = (const float*)d_in[18];
    const float* bp       = (const float*)d_in[19];
    float* out = (float*)d_out;

    float *Q, *K, *V, *Q2, *K2, *V2, *ctxL, *ctxP, *tmpL, *tmpP;
    int *ls, *lc, *ps, *pc;
    cudaGetSymbolAddress((void**)&Q,    g_Q);
    cudaGetSymbolAddress((void**)&K,    g_K);
    cudaGetSymbolAddress((void**)&V,    g_V);
    cudaGetSymbolAddress((void**)&Q2,   g_Q2);
    cudaGetSymbolAddress((void**)&K2,   g_K2);
    cudaGetSymbolAddress((void**)&V2,   g_V2);
    cudaGetSymbolAddress((void**)&ctxL, g_ctxL);
    cudaGetSymbolAddress((void**)&ctxP, g_ctxP);
    cudaGetSymbolAddress((void**)&tmpL, g_tmpL);
    cudaGetSymbolAddress((void**)&tmpP, g_tmpP);
    cudaGetSymbolAddress((void**)&ls,   g_ls);
    cudaGetSymbolAddress((void**)&lc,   g_lc);
    cudaGetSymbolAddress((void**)&ps,   g_ps);
    cudaGetSymbolAddress((void**)&pc,   g_pc);

    cudaFuncSetAttribute(gemm_mma, cudaFuncAttributeMaxDynamicSharedMemorySize, GEMM_SMEM);
    cudaFuncSetAttribute(attn_tiled, cudaFuncAttributeMaxDynamicSharedMemorySize, ATTN_SMEM_BYTES);

    ranges_kernel<<<1, 64>>>(lig_batch, pro_batch);

    // all 6 QKV projections, one launch: ops 0-2 lig (16 tiles), 3-5 pro (128)
    MmaOps gq;
    gq.X[0] = lig; gq.X[1] = lig; gq.X[2] = lig;
    gq.X[3] = pro; gq.X[4] = pro; gq.X[5] = pro;
    gq.W[0] = Wq_lig; gq.W[1] = Wk_lig; gq.W[2] = Wv_lig;
    gq.W[3] = Wk_pro; gq.W[4] = Wv_pro; gq.W[5] = Wq_pro;
    gq.Y[0] = Q;  gq.Y[1] = K2; gq.Y[2] = V2;
    gq.Y[3] = K;  gq.Y[4] = V;  gq.Y[5] = Q2;
    gq.lig_ops = 3;
    gemm_mma<<<dim3(3 * 16 + 3 * 128, 2), 256, GEMM_SMEM>>>(gq);

    // both attention directions, one launch (long lig blocks first)
    AttnSide aL, aP;
    aL.Q = Q;  aL.K = K;  aL.V = V;  aL.qpos = lig_pos; aL.kpos = pro_pos;
    aL.qbatch = lig_batch; aL.kbatch = pro_batch; aL.kstart = ps; aL.kcount = pc;
    aL.ctx = ctxL; aL.nblk = NLIG / TQA;
    aP.Q = Q2; aP.K = K2; aP.V = V2; aP.qpos = pro_pos; aP.kpos = lig_pos;
    aP.qbatch = pro_batch; aP.kbatch = lig_batch; aP.kstart = ls; aP.kcount = lc;
    aP.ctx = ctxP; aP.nblk = NPRO / TQA;
    attn_tiled<<<NLIG / TQA + NPRO / TQA, 256, ATTN_SMEM_BYTES>>>(aL, aP);

    // both output projections, one launch
    MmaOps go;
    go.X[0] = ctxL; go.X[1] = ctxP;
    go.W[0] = Wout_lig; go.W[1] = Wout_pro;
    go.Y[0] = tmpL; go.Y[1] = tmpP;
    go.X[2] = go.X[3] = go.X[4] = go.X[5] = ctxL;
    go.W[2] = go.W[3] = go.W[4] = go.W[5] = Wout_lig;
    go.Y[2] = go.Y[3] = go.Y[4] = go.Y[5] = tmpL;
    go.lig_ops = 1;
    gemm_mma<<<dim3(16 + 128, 2), 256, GEMM_SMEM>>>(go);

    // both layernorms, one launch
    ln2_kernel<<<(NLIG + NPRO) / 4, 128>>>(lig, pro, tmpL, tmpP,
                                           bout_lig, bout_pro, gl, bl, gp, bp, out);
}